// round 1
// baseline (speedup 1.0000x reference)
#include <cuda_runtime.h>
#include <math.h>
#include <stddef.h>

// Problem constants (B=1)
#define S_LEN  4096
#define DMODEL 512
#define IN_DIM 512
#define NHEAD  8
#define DKH    64          // head dim

// ---------------- scratch (device globals; no allocations allowed) ----------
__device__ float g_Q[S_LEN * DMODEL];
__device__ float g_K[S_LEN * DMODEL];
__device__ float g_V[S_LEN * DMODEL];
__device__ float g_AO[S_LEN * DMODEL];

// ============================================================================
// Generic fp32 GEMM tile:  C[m0:m0+128, n0:n0+128] = A[M,K] * B[N,K]^T + bias
// 256 threads, 8x8 micro-tile per thread, BK=16, both operands transposed in
// smem ([BK][128+4], 16B-aligned rows) for vectorized LDS.128 reads.
// ============================================================================
#define GBM 128
#define GBN 128
#define GBK 16

__device__ __forceinline__ void gemm_tile_body(
    const float* __restrict__ A, const float* __restrict__ B,
    const float* __restrict__ bias, float* __restrict__ C,
    int K, int ldc, int m0, int n0,
    float As[GBK][GBM + 4], float Bs[GBK][GBN + 4])
{
    const int tid = threadIdx.x;         // 256
    const int tx  = tid & 15;
    const int ty  = tid >> 4;
    const int r   = tid >> 2;            // 0..63
    const int cg  = (tid & 3) * 4;       // 0,4,8,12

    float c[8][8];
#pragma unroll
    for (int i = 0; i < 8; i++)
#pragma unroll
        for (int j = 0; j < 8; j++) c[i][j] = 0.f;

    for (int k0 = 0; k0 < K; k0 += GBK) {
        // prefetch global into registers
        float4 a0 = *(const float4*)(A + (size_t)(m0 + r)      * K + k0 + cg);
        float4 a1 = *(const float4*)(A + (size_t)(m0 + r + 64) * K + k0 + cg);
        float4 b0 = *(const float4*)(B + (size_t)(n0 + r)      * K + k0 + cg);
        float4 b1 = *(const float4*)(B + (size_t)(n0 + r + 64) * K + k0 + cg);
        __syncthreads();
        As[cg + 0][r]      = a0.x; As[cg + 1][r]      = a0.y;
        As[cg + 2][r]      = a0.z; As[cg + 3][r]      = a0.w;
        As[cg + 0][r + 64] = a1.x; As[cg + 1][r + 64] = a1.y;
        As[cg + 2][r + 64] = a1.z; As[cg + 3][r + 64] = a1.w;
        Bs[cg + 0][r]      = b0.x; Bs[cg + 1][r]      = b0.y;
        Bs[cg + 2][r]      = b0.z; Bs[cg + 3][r]      = b0.w;
        Bs[cg + 0][r + 64] = b1.x; Bs[cg + 1][r + 64] = b1.y;
        Bs[cg + 2][r + 64] = b1.z; Bs[cg + 3][r + 64] = b1.w;
        __syncthreads();
#pragma unroll
        for (int kk = 0; kk < GBK; kk++) {
            float a[8], b[8];
            *(float4*)(a)     = *(const float4*)(&As[kk][ty * 8]);
            *(float4*)(a + 4) = *(const float4*)(&As[kk][ty * 8 + 4]);
            *(float4*)(b)     = *(const float4*)(&Bs[kk][tx * 4]);
            *(float4*)(b + 4) = *(const float4*)(&Bs[kk][64 + tx * 4]);
#pragma unroll
            for (int i = 0; i < 8; i++)
#pragma unroll
                for (int j = 0; j < 8; j++)
                    c[i][j] = fmaf(a[i], b[j], c[i][j]);
        }
    }

    float4 bv0 = *(const float4*)(bias + n0 + tx * 4);
    float4 bv1 = *(const float4*)(bias + n0 + 64 + tx * 4);
#pragma unroll
    for (int i = 0; i < 8; i++) {
        const size_t row = (size_t)(m0 + ty * 8 + i);
        float4 o0 = make_float4(c[i][0] + bv0.x, c[i][1] + bv0.y,
                                c[i][2] + bv0.z, c[i][3] + bv0.w);
        float4 o1 = make_float4(c[i][4] + bv1.x, c[i][5] + bv1.y,
                                c[i][6] + bv1.z, c[i][7] + bv1.w);
        *(float4*)(C + row * ldc + n0 + tx * 4)      = o0;
        *(float4*)(C + row * ldc + n0 + 64 + tx * 4) = o1;
    }
}

// Fused QKV projection: grid (12, 32). n-block 0..11 selects matrix & column.
__global__ __launch_bounds__(256) void qkv_gemm_kernel(
    const float* __restrict__ x,
    const float* __restrict__ wq, const float* __restrict__ bq,
    const float* __restrict__ wk, const float* __restrict__ bk,
    const float* __restrict__ wv, const float* __restrict__ bv,
    float* __restrict__ Qo, float* __restrict__ Ko, float* __restrict__ Vo)
{
    __shared__ float As[GBK][GBM + 4];
    __shared__ float Bs[GBK][GBN + 4];
    const int nb  = blockIdx.x;          // 0..11
    const int mat = nb >> 2;             // 0:Q 1:K 2:V
    const int n0  = (nb & 3) * GBN;
    const int m0  = blockIdx.y * GBM;
    const float* B    = (mat == 0) ? wq : (mat == 1) ? wk : wv;
    const float* bias = (mat == 0) ? bq : (mat == 1) ? bk : bv;
    float* C          = (mat == 0) ? Qo : (mat == 1) ? Ko : Vo;
    gemm_tile_body(x, B, bias, C, IN_DIM, DMODEL, m0, n0, As, Bs);
}

// Plain GEMM with bias (dense output projection): grid (N/128, M/128)
__global__ __launch_bounds__(256) void gemm_tn_bias_kernel(
    const float* __restrict__ A, const float* __restrict__ B,
    const float* __restrict__ bias, float* __restrict__ C, int K, int ldc)
{
    __shared__ float As[GBK][GBM + 4];
    __shared__ float Bs[GBK][GBN + 4];
    gemm_tile_body(A, B, bias, C, K, ldc,
                   blockIdx.y * GBM, blockIdx.x * GBN, As, Bs);
}

// ============================================================================
// Flash attention (fp32, streaming softmax).
// Grid: (S/BQ, NHEAD). 256 threads = 16x16; thread (ty,tx) owns an 8x4
// microtile of the 128x64 score block and an 8x4 microtile of the 128x64 O.
// Head h uses rows [h*4096, h*4096+4096) of the flat [32768,64] Q/K/V view
// (this reproduces the reference's reshape-based head split exactly).
// ============================================================================
#define BQ  128
#define BKC 64

#define QS(r, c) Qs[(r) * (DKH + 1) + (c)]
#define KS(r, c) Ks[(r) * (DKH + 1) + (c)]
#define VS(r, c) Vs[(r) * (DKH + 1) + (c)]
#define PS(r, c) Ps[(r) * (BQ + 1) + (c)]

#define ATTN_SMEM_FLOATS (BQ * (DKH + 1) + 2 * BKC * (DKH + 1) + BKC * (BQ + 1))
#define ATTN_SMEM_BYTES  (ATTN_SMEM_FLOATS * 4)

__global__ __launch_bounds__(256, 2) void attn_kernel(
    const float* __restrict__ Q, const float* __restrict__ K,
    const float* __restrict__ V, const int* __restrict__ mask,
    float* __restrict__ O)
{
    extern __shared__ float sm[];
    float* Qs = sm;                               // [BQ][DKH+1]
    float* Ks = Qs + BQ * (DKH + 1);              // [BKC][DKH+1]
    float* Vs = Ks + BKC * (DKH + 1);             // [BKC][DKH+1]
    float* Ps = Vs + BKC * (DKH + 1);             // [BKC][BQ+1] (P transposed)

    const int tid = threadIdx.x;
    const int tx  = tid & 15;
    const int ty  = tid >> 4;
    const int h   = blockIdx.y;
    const int qb  = blockIdx.x;

    const float* Qg = Q + ((size_t)h * S_LEN + (size_t)qb * BQ) * DKH;
    const float* Kg = K + (size_t)h * S_LEN * DKH;
    const float* Vg = V + (size_t)h * S_LEN * DKH;

    // Load Q tile (128x64) once
#pragma unroll
    for (int p = 0; p < 8; p++) {
        int f   = tid + p * 256;      // float4 index, < 2048
        int row = f >> 4;
        int col = (f & 15) * 4;
        float4 v4 = *(const float4*)(Qg + (size_t)row * DKH + col);
        QS(row, col + 0) = v4.x; QS(row, col + 1) = v4.y;
        QS(row, col + 2) = v4.z; QS(row, col + 3) = v4.w;
    }

    float m[8], l[8], o[8][4];
#pragma unroll
    for (int i = 0; i < 8; i++) {
        m[i] = -INFINITY; l[i] = 0.f;
#pragma unroll
        for (int j = 0; j < 4; j++) o[i][j] = 0.f;
    }

    for (int kb = 0; kb < S_LEN / BKC; kb++) {
        __syncthreads();   // prev iter's smem reads done (also covers Q load)
        // Load K & V chunks (64x64 each)
#pragma unroll
        for (int p = 0; p < 4; p++) {
            int f   = tid + p * 256;   // < 1024
            int row = f >> 4;
            int col = (f & 15) * 4;
            size_t goff = (size_t)(kb * BKC + row) * DKH + col;
            float4 kv4 = *(const float4*)(Kg + goff);
            float4 vv4 = *(const float4*)(Vg + goff);
            KS(row, col + 0) = kv4.x; KS(row, col + 1) = kv4.y;
            KS(row, col + 2) = kv4.z; KS(row, col + 3) = kv4.w;
            VS(row, col + 0) = vv4.x; VS(row, col + 1) = vv4.y;
            VS(row, col + 2) = vv4.z; VS(row, col + 3) = vv4.w;
        }
        __syncthreads();

        // S = Q * K^T  (8x4 microtile per thread)
        float s[8][4];
#pragma unroll
        for (int i = 0; i < 8; i++)
#pragma unroll
            for (int j = 0; j < 4; j++) s[i][j] = 0.f;

#pragma unroll 8
        for (int kk = 0; kk < DKH; kk++) {
            float qv[8], kv[4];
#pragma unroll
            for (int i = 0; i < 8; i++) qv[i] = QS(ty * 8 + i, kk);
#pragma unroll
            for (int j = 0; j < 4; j++) kv[j] = KS(tx * 4 + j, kk);
#pragma unroll
            for (int i = 0; i < 8; i++)
#pragma unroll
                for (int j = 0; j < 4; j++)
                    s[i][j] = fmaf(qv[i], kv[j], s[i][j]);
        }

        // mask + online softmax (rows span 16 lanes: lanes (ty%2)*16 + tx)
#pragma unroll
        for (int i = 0; i < 8; i++) {
            const int4 mm = *(const int4*)(
                mask + (size_t)(qb * BQ + ty * 8 + i) * S_LEN + kb * BKC + tx * 4);
            s[i][0] = s[i][0] * 0.125f - 1e9f * (float)mm.x;
            s[i][1] = s[i][1] * 0.125f - 1e9f * (float)mm.y;
            s[i][2] = s[i][2] * 0.125f - 1e9f * (float)mm.z;
            s[i][3] = s[i][3] * 0.125f - 1e9f * (float)mm.w;

            float rm = fmaxf(fmaxf(s[i][0], s[i][1]), fmaxf(s[i][2], s[i][3]));
            rm = fmaxf(rm, __shfl_xor_sync(0xffffffffu, rm, 8));
            rm = fmaxf(rm, __shfl_xor_sync(0xffffffffu, rm, 4));
            rm = fmaxf(rm, __shfl_xor_sync(0xffffffffu, rm, 2));
            rm = fmaxf(rm, __shfl_xor_sync(0xffffffffu, rm, 1));

            float mn = fmaxf(m[i], rm);
            float sc = __expf(m[i] - mn);
            m[i] = mn;

            float rs = 0.f;
#pragma unroll
            for (int j = 0; j < 4; j++) {
                s[i][j] = __expf(s[i][j] - mn);
                rs += s[i][j];
            }
            rs += __shfl_xor_sync(0xffffffffu, rs, 8);
            rs += __shfl_xor_sync(0xffffffffu, rs, 4);
            rs += __shfl_xor_sync(0xffffffffu, rs, 2);
            rs += __shfl_xor_sync(0xffffffffu, rs, 1);

            l[i] = l[i] * sc + rs;
#pragma unroll
            for (int j = 0; j < 4; j++) {
                o[i][j] *= sc;
                PS(tx * 4 + j, ty * 8 + i) = s[i][j];   // store P transposed
            }
        }
        __syncthreads();

        // O += P * V
#pragma unroll 8
        for (int kk = 0; kk < BKC; kk++) {
            float pv[8], vv[4];
#pragma unroll
            for (int i = 0; i < 8; i++) pv[i] = PS(kk, ty * 8 + i);
#pragma unroll
            for (int j = 0; j < 4; j++) vv[j] = VS(kk, tx * 4 + j);
#pragma unroll
            for (int i = 0; i < 8; i++)
#pragma unroll
                for (int j = 0; j < 4; j++)
                    o[i][j] = fmaf(pv[i], vv[j], o[i][j]);
        }
    }

    // Write normalized output: AttnOut[token][h*64 + d]
#pragma unroll
    for (int i = 0; i < 8; i++) {
        float inv = 1.0f / l[i];
        float4 r4 = make_float4(o[i][0] * inv, o[i][1] * inv,
                                o[i][2] * inv, o[i][3] * inv);
        *(float4*)(O + (size_t)(qb * BQ + ty * 8 + i) * DMODEL + h * DKH + tx * 4) = r4;
    }
}

// ============================================================================
extern "C" void kernel_launch(void* const* d_in, const int* in_sizes, int n_in,
                              void* d_out, int out_size)
{
    const float* x       = (const float*)d_in[0];
    const int*   mask    = (const int*)  d_in[1];
    const float* wq_w    = (const float*)d_in[2];
    const float* wq_b    = (const float*)d_in[3];
    const float* wk_w    = (const float*)d_in[4];
    const float* wk_b    = (const float*)d_in[5];
    const float* wv_w    = (const float*)d_in[6];
    const float* wv_b    = (const float*)d_in[7];
    const float* dense_w = (const float*)d_in[8];
    const float* dense_b = (const float*)d_in[9];
    float* out = (float*)d_out;

    float *Qp, *Kp, *Vp, *AOp;
    cudaGetSymbolAddress((void**)&Qp,  g_Q);
    cudaGetSymbolAddress((void**)&Kp,  g_K);
    cudaGetSymbolAddress((void**)&Vp,  g_V);
    cudaGetSymbolAddress((void**)&AOp, g_AO);

    cudaFuncSetAttribute(attn_kernel,
                         cudaFuncAttributeMaxDynamicSharedMemorySize,
                         ATTN_SMEM_BYTES);

    // 1) Fused QKV projections
    qkv_gemm_kernel<<<dim3(12, S_LEN / GBM), 256>>>(
        x, wq_w, wq_b, wk_w, wk_b, wv_w, wv_b, Qp, Kp, Vp);

    // 2) Masked flash attention (all 8 heads)
    attn_kernel<<<dim3(S_LEN / BQ, NHEAD), 256, ATTN_SMEM_BYTES>>>(
        Qp, Kp, Vp, mask, AOp);

    // 3) Dense output projection
    gemm_tn_bias_kernel<<<dim3(DMODEL / GBN, S_LEN / GBM), 256>>>(
        AOp, dense_w, dense_b, out, DMODEL, DMODEL);
}

// round 2
// speedup vs baseline: 1.8368x; 1.8368x over previous
#include <cuda_runtime.h>
#include <math.h>
#include <stddef.h>

// Problem constants (B=1)
#define S_LEN  4096
#define DMODEL 512
#define IN_DIM 512
#define NHEAD  8
#define DKH    64          // head dim

// ---------------- scratch (device globals; no allocations allowed) ----------
__device__ float g_Q[S_LEN * DMODEL];
__device__ float g_K[S_LEN * DMODEL];
__device__ float g_V[S_LEN * DMODEL];
__device__ float g_AO[S_LEN * DMODEL];

// ============================================================================
// Generic fp32 GEMM tile:  C[m0:m0+128, n0:n0+128] = A[M,K] * B[N,K]^T + bias
// ============================================================================
#define GBM 128
#define GBN 128
#define GBK 16

__device__ __forceinline__ void gemm_tile_body(
    const float* __restrict__ A, const float* __restrict__ B,
    const float* __restrict__ bias, float* __restrict__ C,
    int K, int ldc, int m0, int n0,
    float As[GBK][GBM + 4], float Bs[GBK][GBN + 4])
{
    const int tid = threadIdx.x;         // 256
    const int tx  = tid & 15;
    const int ty  = tid >> 4;
    const int r   = tid >> 2;            // 0..63
    const int cg  = (tid & 3) * 4;       // 0,4,8,12

    float c[8][8];
#pragma unroll
    for (int i = 0; i < 8; i++)
#pragma unroll
        for (int j = 0; j < 8; j++) c[i][j] = 0.f;

    for (int k0 = 0; k0 < K; k0 += GBK) {
        float4 a0 = *(const float4*)(A + (size_t)(m0 + r)      * K + k0 + cg);
        float4 a1 = *(const float4*)(A + (size_t)(m0 + r + 64) * K + k0 + cg);
        float4 b0 = *(const float4*)(B + (size_t)(n0 + r)      * K + k0 + cg);
        float4 b1 = *(const float4*)(B + (size_t)(n0 + r + 64) * K + k0 + cg);
        __syncthreads();
        As[cg + 0][r]      = a0.x; As[cg + 1][r]      = a0.y;
        As[cg + 2][r]      = a0.z; As[cg + 3][r]      = a0.w;
        As[cg + 0][r + 64] = a1.x; As[cg + 1][r + 64] = a1.y;
        As[cg + 2][r + 64] = a1.z; As[cg + 3][r + 64] = a1.w;
        Bs[cg + 0][r]      = b0.x; Bs[cg + 1][r]      = b0.y;
        Bs[cg + 2][r]      = b0.z; Bs[cg + 3][r]      = b0.w;
        Bs[cg + 0][r + 64] = b1.x; Bs[cg + 1][r + 64] = b1.y;
        Bs[cg + 2][r + 64] = b1.z; Bs[cg + 3][r + 64] = b1.w;
        __syncthreads();
#pragma unroll
        for (int kk = 0; kk < GBK; kk++) {
            float a[8], b[8];
            *(float4*)(a)     = *(const float4*)(&As[kk][ty * 8]);
            *(float4*)(a + 4) = *(const float4*)(&As[kk][ty * 8 + 4]);
            *(float4*)(b)     = *(const float4*)(&Bs[kk][tx * 4]);
            *(float4*)(b + 4) = *(const float4*)(&Bs[kk][64 + tx * 4]);
#pragma unroll
            for (int i = 0; i < 8; i++)
#pragma unroll
                for (int j = 0; j < 8; j++)
                    c[i][j] = fmaf(a[i], b[j], c[i][j]);
        }
    }

    float4 bv0 = *(const float4*)(bias + n0 + tx * 4);
    float4 bv1 = *(const float4*)(bias + n0 + 64 + tx * 4);
#pragma unroll
    for (int i = 0; i < 8; i++) {
        const size_t row = (size_t)(m0 + ty * 8 + i);
        float4 o0 = make_float4(c[i][0] + bv0.x, c[i][1] + bv0.y,
                                c[i][2] + bv0.z, c[i][3] + bv0.w);
        float4 o1 = make_float4(c[i][4] + bv1.x, c[i][5] + bv1.y,
                                c[i][6] + bv1.z, c[i][7] + bv1.w);
        *(float4*)(C + row * ldc + n0 + tx * 4)      = o0;
        *(float4*)(C + row * ldc + n0 + 64 + tx * 4) = o1;
    }
}

__global__ __launch_bounds__(256) void qkv_gemm_kernel(
    const float* __restrict__ x,
    const float* __restrict__ wq, const float* __restrict__ bq,
    const float* __restrict__ wk, const float* __restrict__ bk,
    const float* __restrict__ wv, const float* __restrict__ bv,
    float* __restrict__ Qo, float* __restrict__ Ko, float* __restrict__ Vo)
{
    __shared__ float As[GBK][GBM + 4];
    __shared__ float Bs[GBK][GBN + 4];
    const int nb  = blockIdx.x;          // 0..11
    const int mat = nb >> 2;             // 0:Q 1:K 2:V
    const int n0  = (nb & 3) * GBN;
    const int m0  = blockIdx.y * GBM;
    const float* B    = (mat == 0) ? wq : (mat == 1) ? wk : wv;
    const float* bias = (mat == 0) ? bq : (mat == 1) ? bk : bv;
    float* C          = (mat == 0) ? Qo : (mat == 1) ? Ko : Vo;
    gemm_tile_body(x, B, bias, C, IN_DIM, DMODEL, m0, n0, As, Bs);
}

__global__ __launch_bounds__(256) void gemm_tn_bias_kernel(
    const float* __restrict__ A, const float* __restrict__ B,
    const float* __restrict__ bias, float* __restrict__ C, int K, int ldc)
{
    __shared__ float As[GBK][GBM + 4];
    __shared__ float Bs[GBK][GBN + 4];
    gemm_tile_body(A, B, bias, C, K, ldc,
                   blockIdx.y * GBM, blockIdx.x * GBN, As, Bs);
}

// ============================================================================
// Tensor-core flash attention (tf32 mma.sync.m16n8k8, fp32 accumulate).
// Grid (S/128, 8 heads). 256 threads = 8 warps; warp w owns query rows
// [w*16, w*16+16) of the 128-row Q tile. K/V streamed in 64-row chunks.
// Head h uses rows [h*4096, (h+1)*4096) of the flat [32768,64] Q/K/V view
// (faithful to the reference's reshape-based head split).
// ============================================================================
#define BQ  128
#define BKC 64
#define LQ  68    // smem row strides (floats), chosen for conflict-free frags
#define LK  68
#define LV  72
#define LP  68

#define ATTN_SMEM_FLOATS (BQ * LQ + BKC * LK + BKC * LV + BQ * LP)
#define ATTN_SMEM_BYTES  (ATTN_SMEM_FLOATS * 4)

__device__ __forceinline__ unsigned f2tf32(float x) {
    unsigned u;
    asm("cvt.rna.tf32.f32 %0, %1;" : "=r"(u) : "f"(x));
    return u;
}

__device__ __forceinline__ void mma_tf32(float c[4],
    unsigned a0, unsigned a1, unsigned a2, unsigned a3,
    unsigned b0, unsigned b1)
{
    asm volatile(
        "mma.sync.aligned.m16n8k8.row.col.f32.tf32.tf32.f32 "
        "{%0,%1,%2,%3}, {%4,%5,%6,%7}, {%8,%9}, {%0,%1,%2,%3};\n"
        : "+f"(c[0]), "+f"(c[1]), "+f"(c[2]), "+f"(c[3])
        : "r"(a0), "r"(a1), "r"(a2), "r"(a3), "r"(b0), "r"(b1));
}

__global__ __launch_bounds__(256, 1) void attn_tc_kernel(
    const float* __restrict__ Q, const float* __restrict__ K,
    const float* __restrict__ V, const int* __restrict__ mask,
    float* __restrict__ O)
{
    extern __shared__ float sm[];
    float* Qs = sm;                 // [BQ][LQ]  (tf32 bits)
    float* Ks = Qs + BQ * LQ;       // [BKC][LK]
    float* Vs = Ks + BKC * LK;      // [BKC][LV]
    float* Ps = Vs + BKC * LV;      // [BQ][LP]

    const int tid  = threadIdx.x;
    const int w    = tid >> 5;
    const int lane = tid & 31;
    const int g    = lane >> 2;     // 0..7
    const int tig  = lane & 3;      // 0..3
    const int h    = blockIdx.y;
    const int qb   = blockIdx.x;
    const int w16  = w * 16;

    const float* Qg = Q + ((size_t)h * S_LEN + (size_t)qb * BQ) * DKH;
    const float* Kg = K + (size_t)h * S_LEN * DKH;
    const float* Vg = V + (size_t)h * S_LEN * DKH;

    // Load + convert Q tile (128x64) once
#pragma unroll
    for (int p = 0; p < 8; p++) {
        int f   = tid + p * 256;
        int row = f >> 4;
        int col = (f & 15) * 4;
        float4 v4 = *(const float4*)(Qg + (size_t)row * DKH + col);
        Qs[row * LQ + col + 0] = __uint_as_float(f2tf32(v4.x));
        Qs[row * LQ + col + 1] = __uint_as_float(f2tf32(v4.y));
        Qs[row * LQ + col + 2] = __uint_as_float(f2tf32(v4.z));
        Qs[row * LQ + col + 3] = __uint_as_float(f2tf32(v4.w));
    }

    // Softmax state: this thread owns rows (w16+g) and (w16+g+8)
    float m0 = -INFINITY, m1 = -INFINITY, l0 = 0.f, l1 = 0.f;
    float o[8][4];
#pragma unroll
    for (int nt = 0; nt < 8; nt++)
#pragma unroll
        for (int j = 0; j < 4; j++) o[nt][j] = 0.f;

    const int row0 = qb * BQ + w16 + g;
    const int row1 = row0 + 8;
    const int* mrow0 = mask + (size_t)row0 * S_LEN + 2 * tig;
    const int* mrow1 = mask + (size_t)row1 * S_LEN + 2 * tig;

    for (int kb = 0; kb < S_LEN / BKC; kb++) {
        __syncthreads();                      // prev-iter smem reads complete
        // Load + convert K/V chunk (64x64 each)
#pragma unroll
        for (int p = 0; p < 4; p++) {
            int f   = tid + p * 256;
            int row = f >> 4;
            int col = (f & 15) * 4;
            size_t goff = (size_t)(kb * BKC + row) * DKH + col;
            float4 kv4 = *(const float4*)(Kg + goff);
            float4 vv4 = *(const float4*)(Vg + goff);
            Ks[row * LK + col + 0] = __uint_as_float(f2tf32(kv4.x));
            Ks[row * LK + col + 1] = __uint_as_float(f2tf32(kv4.y));
            Ks[row * LK + col + 2] = __uint_as_float(f2tf32(kv4.z));
            Ks[row * LK + col + 3] = __uint_as_float(f2tf32(kv4.w));
            Vs[row * LV + col + 0] = __uint_as_float(f2tf32(vv4.x));
            Vs[row * LV + col + 1] = __uint_as_float(f2tf32(vv4.y));
            Vs[row * LV + col + 2] = __uint_as_float(f2tf32(vv4.z));
            Vs[row * LV + col + 3] = __uint_as_float(f2tf32(vv4.w));
        }
        __syncthreads();

        // ---- S = Q * K^T : 16x64 per warp, 8 mma n-tiles ----
        float s[8][4];
#pragma unroll
        for (int nt = 0; nt < 8; nt++)
#pragma unroll
            for (int j = 0; j < 4; j++) s[nt][j] = 0.f;

#pragma unroll
        for (int kk = 0; kk < 8; kk++) {
            unsigned a0 = __float_as_uint(Qs[(w16 + g)     * LQ + kk * 8 + tig]);
            unsigned a1 = __float_as_uint(Qs[(w16 + g + 8) * LQ + kk * 8 + tig]);
            unsigned a2 = __float_as_uint(Qs[(w16 + g)     * LQ + kk * 8 + tig + 4]);
            unsigned a3 = __float_as_uint(Qs[(w16 + g + 8) * LQ + kk * 8 + tig + 4]);
#pragma unroll
            for (int nt = 0; nt < 8; nt++) {
                unsigned b0 = __float_as_uint(Ks[(nt * 8 + g) * LK + kk * 8 + tig]);
                unsigned b1 = __float_as_uint(Ks[(nt * 8 + g) * LK + kk * 8 + tig + 4]);
                mma_tf32(s[nt], a0, a1, a2, a3, b0, b1);
            }
        }

        // ---- mask + online softmax ----
        const int kbase = kb * BKC;
        float mx0 = -INFINITY, mx1 = -INFINITY;
#pragma unroll
        for (int nt = 0; nt < 8; nt++) {
            int2 mm0 = *(const int2*)(mrow0 + kbase + nt * 8);
            int2 mm1 = *(const int2*)(mrow1 + kbase + nt * 8);
            s[nt][0] = s[nt][0] * 0.125f - 1e9f * (float)mm0.x;
            s[nt][1] = s[nt][1] * 0.125f - 1e9f * (float)mm0.y;
            s[nt][2] = s[nt][2] * 0.125f - 1e9f * (float)mm1.x;
            s[nt][3] = s[nt][3] * 0.125f - 1e9f * (float)mm1.y;
            mx0 = fmaxf(mx0, fmaxf(s[nt][0], s[nt][1]));
            mx1 = fmaxf(mx1, fmaxf(s[nt][2], s[nt][3]));
        }
        mx0 = fmaxf(mx0, __shfl_xor_sync(0xffffffffu, mx0, 1));
        mx0 = fmaxf(mx0, __shfl_xor_sync(0xffffffffu, mx0, 2));
        mx1 = fmaxf(mx1, __shfl_xor_sync(0xffffffffu, mx1, 1));
        mx1 = fmaxf(mx1, __shfl_xor_sync(0xffffffffu, mx1, 2));

        float mn0 = fmaxf(m0, mx0), mn1 = fmaxf(m1, mx1);
        float sc0 = __expf(m0 - mn0), sc1 = __expf(m1 - mn1);
        m0 = mn0; m1 = mn1;

        float rs0 = 0.f, rs1 = 0.f;
#pragma unroll
        for (int nt = 0; nt < 8; nt++) {
            float p0 = __expf(s[nt][0] - mn0);
            float p1 = __expf(s[nt][1] - mn0);
            float p2 = __expf(s[nt][2] - mn1);
            float p3 = __expf(s[nt][3] - mn1);
            rs0 += p0 + p1;
            rs1 += p2 + p3;
            *(float2*)&Ps[(w16 + g)     * LP + nt * 8 + 2 * tig] =
                make_float2(__uint_as_float(f2tf32(p0)), __uint_as_float(f2tf32(p1)));
            *(float2*)&Ps[(w16 + g + 8) * LP + nt * 8 + 2 * tig] =
                make_float2(__uint_as_float(f2tf32(p2)), __uint_as_float(f2tf32(p3)));
            o[nt][0] *= sc0; o[nt][1] *= sc0;
            o[nt][2] *= sc1; o[nt][3] *= sc1;
        }
        rs0 += __shfl_xor_sync(0xffffffffu, rs0, 1);
        rs0 += __shfl_xor_sync(0xffffffffu, rs0, 2);
        rs1 += __shfl_xor_sync(0xffffffffu, rs1, 1);
        rs1 += __shfl_xor_sync(0xffffffffu, rs1, 2);
        l0 = l0 * sc0 + rs0;
        l1 = l1 * sc1 + rs1;

        __syncwarp();   // P stores visible within warp (only this warp reads them)

        // ---- O += P * V ----
#pragma unroll
        for (int kc = 0; kc < 8; kc++) {
            unsigned a0 = __float_as_uint(Ps[(w16 + g)     * LP + kc * 8 + tig]);
            unsigned a1 = __float_as_uint(Ps[(w16 + g + 8) * LP + kc * 8 + tig]);
            unsigned a2 = __float_as_uint(Ps[(w16 + g)     * LP + kc * 8 + tig + 4]);
            unsigned a3 = __float_as_uint(Ps[(w16 + g + 8) * LP + kc * 8 + tig + 4]);
#pragma unroll
            for (int nt = 0; nt < 8; nt++) {
                unsigned b0 = __float_as_uint(Vs[(kc * 8 + tig)     * LV + nt * 8 + g]);
                unsigned b1 = __float_as_uint(Vs[(kc * 8 + tig + 4) * LV + nt * 8 + g]);
                mma_tf32(o[nt], a0, a1, a2, a3, b0, b1);
            }
        }
    }

    // Normalize + write AttnOut[token][h*64 + d]
    float inv0 = 1.0f / l0, inv1 = 1.0f / l1;
    float* O0 = O + (size_t)row0 * DMODEL + h * DKH + 2 * tig;
    float* O1 = O + (size_t)row1 * DMODEL + h * DKH + 2 * tig;
#pragma unroll
    for (int nt = 0; nt < 8; nt++) {
        *(float2*)(O0 + nt * 8) = make_float2(o[nt][0] * inv0, o[nt][1] * inv0);
        *(float2*)(O1 + nt * 8) = make_float2(o[nt][2] * inv1, o[nt][3] * inv1);
    }
}

// ============================================================================
extern "C" void kernel_launch(void* const* d_in, const int* in_sizes, int n_in,
                              void* d_out, int out_size)
{
    const float* x       = (const float*)d_in[0];
    const int*   mask    = (const int*)  d_in[1];
    const float* wq_w    = (const float*)d_in[2];
    const float* wq_b    = (const float*)d_in[3];
    const float* wk_w    = (const float*)d_in[4];
    const float* wk_b    = (const float*)d_in[5];
    const float* wv_w    = (const float*)d_in[6];
    const float* wv_b    = (const float*)d_in[7];
    const float* dense_w = (const float*)d_in[8];
    const float* dense_b = (const float*)d_in[9];
    float* out = (float*)d_out;

    float *Qp, *Kp, *Vp, *AOp;
    cudaGetSymbolAddress((void**)&Qp,  g_Q);
    cudaGetSymbolAddress((void**)&Kp,  g_K);
    cudaGetSymbolAddress((void**)&Vp,  g_V);
    cudaGetSymbolAddress((void**)&AOp, g_AO);

    cudaFuncSetAttribute(attn_tc_kernel,
                         cudaFuncAttributeMaxDynamicSharedMemorySize,
                         ATTN_SMEM_BYTES);

    // 1) Fused QKV projections (fp32 CUDA cores, R2 target for tensorization)
    qkv_gemm_kernel<<<dim3(12, S_LEN / GBM), 256>>>(
        x, wq_w, wq_b, wk_w, wk_b, wv_w, wv_b, Qp, Kp, Vp);

    // 2) Masked flash attention on tensor cores (tf32)
    attn_tc_kernel<<<dim3(S_LEN / BQ, NHEAD), 256, ATTN_SMEM_BYTES>>>(
        Qp, Kp, Vp, mask, AOp);

    // 3) Dense output projection
    gemm_tn_bias_kernel<<<dim3(DMODEL / GBN, S_LEN / GBM), 256>>>(
        AOp, dense_w, dense_b, out, DMODEL, DMODEL);
}

// round 3
// speedup vs baseline: 2.7900x; 1.5190x over previous
#include <cuda_runtime.h>
#include <math.h>
#include <stddef.h>

// Problem constants (B=1)
#define S_LEN  4096
#define DMODEL 512
#define IN_DIM 512
#define NHEAD  8
#define DKH    64          // head dim

// ---------------- scratch (device globals; no allocations allowed) ----------
__device__ float g_Q[S_LEN * DMODEL];
__device__ float g_K[S_LEN * DMODEL];
__device__ float g_V[S_LEN * DMODEL];
__device__ float g_AO[S_LEN * DMODEL];
__device__ unsigned long long g_MB[S_LEN * (S_LEN / 64)];   // bit-packed mask

// ---------------- tf32 helpers ----------------------------------------------
__device__ __forceinline__ unsigned f2tf32(float x) {
    unsigned u;
    asm("cvt.rna.tf32.f32 %0, %1;" : "=r"(u) : "f"(x));
    return u;
}
__device__ __forceinline__ float f2tf32f(float x) {
    return __uint_as_float(f2tf32(x));
}

__device__ __forceinline__ void mma_tf32(float c[4],
    unsigned a0, unsigned a1, unsigned a2, unsigned a3,
    unsigned b0, unsigned b1)
{
    asm volatile(
        "mma.sync.aligned.m16n8k8.row.col.f32.tf32.tf32.f32 "
        "{%0,%1,%2,%3}, {%4,%5,%6,%7}, {%8,%9}, {%0,%1,%2,%3};\n"
        : "+f"(c[0]), "+f"(c[1]), "+f"(c[2]), "+f"(c[3])
        : "r"(a0), "r"(a1), "r"(a2), "r"(a3), "r"(b0), "r"(b1));
}

// ============================================================================
// Mask bit-pack: one warp per output uint64 (64 mask columns).
// ============================================================================
__global__ __launch_bounds__(256) void pack_mask_kernel(
    const int* __restrict__ mask, unsigned long long* __restrict__ packed)
{
    const int wid  = (blockIdx.x * blockDim.x + threadIdx.x) >> 5;
    const int lane = threadIdx.x & 31;
    const int row  = wid >> 6;          // q row
    const int word = wid & 63;          // 64-col block
    const int* p = mask + (size_t)row * S_LEN + word * 64;
    unsigned lo = __ballot_sync(0xffffffffu, p[lane]      != 0);
    unsigned hi = __ballot_sync(0xffffffffu, p[lane + 32] != 0);
    if (lane == 0)
        packed[wid] = ((unsigned long long)hi << 32) | (unsigned long long)lo;
}

// ============================================================================
// tf32 tensor-core GEMM: C[m0:+128, n0:+128] = A[M,K]*B[N,K]^T + bias
// 256 thr = 8 warps (4 along M x 2 along N); warp tile 32x64 (2 m-tiles x 8
// n-tiles of m16n8k8). smem tiles [128][20] (LA=20 -> conflict-free frags).
// ============================================================================
#define TGK 16
#define LA  20

__device__ __forceinline__ void gemm_tf32_body(
    const float* __restrict__ A, const float* __restrict__ B,
    const float* __restrict__ bias, float* __restrict__ C,
    int K, int ldc, int m0, int n0, float* As, float* Bs)
{
    const int tid  = threadIdx.x;
    const int w    = tid >> 5, lane = tid & 31;
    const int g    = lane >> 2, tig = lane & 3;
    const int wm   = w & 3, wn = w >> 2;       // 4 x 2 warp grid
    const int r    = tid >> 2;                 // 0..63
    const int cg   = (tid & 3) * 4;            // 0,4,8,12

    float c[2][8][4];
#pragma unroll
    for (int mt = 0; mt < 2; mt++)
#pragma unroll
        for (int nt = 0; nt < 8; nt++)
#pragma unroll
            for (int j = 0; j < 4; j++) c[mt][nt][j] = 0.f;

    for (int k0 = 0; k0 < K; k0 += TGK) {
        float4 a0 = *(const float4*)(A + (size_t)(m0 + r)      * K + k0 + cg);
        float4 a1 = *(const float4*)(A + (size_t)(m0 + r + 64) * K + k0 + cg);
        float4 b0 = *(const float4*)(B + (size_t)(n0 + r)      * K + k0 + cg);
        float4 b1 = *(const float4*)(B + (size_t)(n0 + r + 64) * K + k0 + cg);
        float4 ta0 = make_float4(f2tf32f(a0.x), f2tf32f(a0.y), f2tf32f(a0.z), f2tf32f(a0.w));
        float4 ta1 = make_float4(f2tf32f(a1.x), f2tf32f(a1.y), f2tf32f(a1.z), f2tf32f(a1.w));
        float4 tb0 = make_float4(f2tf32f(b0.x), f2tf32f(b0.y), f2tf32f(b0.z), f2tf32f(b0.w));
        float4 tb1 = make_float4(f2tf32f(b1.x), f2tf32f(b1.y), f2tf32f(b1.z), f2tf32f(b1.w));
        __syncthreads();
        *(float4*)(As + (r)      * LA + cg) = ta0;
        *(float4*)(As + (r + 64) * LA + cg) = ta1;
        *(float4*)(Bs + (r)      * LA + cg) = tb0;
        *(float4*)(Bs + (r + 64) * LA + cg) = tb1;
        __syncthreads();

#pragma unroll
        for (int kk = 0; kk < 2; kk++) {
            unsigned af[2][4];
#pragma unroll
            for (int mt = 0; mt < 2; mt++) {
                const int row = wm * 32 + mt * 16;
                af[mt][0] = __float_as_uint(As[(row + g)     * LA + kk * 8 + tig]);
                af[mt][1] = __float_as_uint(As[(row + g + 8) * LA + kk * 8 + tig]);
                af[mt][2] = __float_as_uint(As[(row + g)     * LA + kk * 8 + tig + 4]);
                af[mt][3] = __float_as_uint(As[(row + g + 8) * LA + kk * 8 + tig + 4]);
            }
#pragma unroll
            for (int nt = 0; nt < 8; nt++) {
                const int brow = wn * 64 + nt * 8 + g;
                unsigned bf0 = __float_as_uint(Bs[brow * LA + kk * 8 + tig]);
                unsigned bf1 = __float_as_uint(Bs[brow * LA + kk * 8 + tig + 4]);
                mma_tf32(c[0][nt], af[0][0], af[0][1], af[0][2], af[0][3], bf0, bf1);
                mma_tf32(c[1][nt], af[1][0], af[1][1], af[1][2], af[1][3], bf0, bf1);
            }
        }
    }

#pragma unroll
    for (int nt = 0; nt < 8; nt++) {
        const int col = n0 + wn * 64 + nt * 8 + 2 * tig;
        const float2 bv = *(const float2*)(bias + col);
#pragma unroll
        for (int mt = 0; mt < 2; mt++) {
            const int row = m0 + wm * 32 + mt * 16 + g;
            *(float2*)(C + (size_t)row * ldc + col) =
                make_float2(c[mt][nt][0] + bv.x, c[mt][nt][1] + bv.y);
            *(float2*)(C + (size_t)(row + 8) * ldc + col) =
                make_float2(c[mt][nt][2] + bv.x, c[mt][nt][3] + bv.y);
        }
    }
}

#define GEMM_SMEM_FLOATS (2 * 128 * LA)

__global__ __launch_bounds__(256, 2) void qkv_gemm_kernel(
    const float* __restrict__ x,
    const float* __restrict__ wq, const float* __restrict__ bq,
    const float* __restrict__ wk, const float* __restrict__ bk,
    const float* __restrict__ wv, const float* __restrict__ bv,
    float* __restrict__ Qo, float* __restrict__ Ko, float* __restrict__ Vo)
{
    __shared__ float sm[GEMM_SMEM_FLOATS];
    const int nb  = blockIdx.x;          // 0..11
    const int mat = nb >> 2;             // 0:Q 1:K 2:V
    const int n0  = (nb & 3) * 128;
    const int m0  = blockIdx.y * 128;
    const float* B    = (mat == 0) ? wq : (mat == 1) ? wk : wv;
    const float* bias = (mat == 0) ? bq : (mat == 1) ? bk : bv;
    float* C          = (mat == 0) ? Qo : (mat == 1) ? Ko : Vo;
    gemm_tf32_body(x, B, bias, C, IN_DIM, DMODEL, m0, n0, sm, sm + 128 * LA);
}

__global__ __launch_bounds__(256, 2) void dense_gemm_kernel(
    const float* __restrict__ A, const float* __restrict__ B,
    const float* __restrict__ bias, float* __restrict__ C)
{
    __shared__ float sm[GEMM_SMEM_FLOATS];
    gemm_tf32_body(A, B, bias, C, DMODEL, DMODEL,
                   blockIdx.y * 128, blockIdx.x * 128, sm, sm + 128 * LA);
}

// ============================================================================
// Tensor-core flash attention (tf32 mma, fp32 accumulate, bit-packed mask).
// Grid (S/128, 8 heads), 256 threads = 8 warps, warp w owns 16 query rows.
// ============================================================================
#define BQ  128
#define BKC 64
#define LQ  68
#define LK  68
#define LV  72
#define LP  68

#define ATTN_SMEM_FLOATS (BQ * LQ + BKC * LK + BKC * LV + BQ * LP)
#define ATTN_SMEM_BYTES  (ATTN_SMEM_FLOATS * 4)

__global__ __launch_bounds__(256, 2) void attn_tc_kernel(
    const float* __restrict__ Q, const float* __restrict__ K,
    const float* __restrict__ V, const unsigned long long* __restrict__ mbits,
    float* __restrict__ O)
{
    extern __shared__ float sm[];
    float* Qs = sm;                 // [BQ][LQ]  (tf32 bits)
    float* Ks = Qs + BQ * LQ;       // [BKC][LK]
    float* Vs = Ks + BKC * LK;      // [BKC][LV]
    float* Ps = Vs + BKC * LV;      // [BQ][LP]

    const int tid  = threadIdx.x;
    const int w    = tid >> 5;
    const int lane = tid & 31;
    const int g    = lane >> 2;     // 0..7
    const int tig  = lane & 3;      // 0..3
    const int h    = blockIdx.y;
    const int qb   = blockIdx.x;
    const int w16  = w * 16;

    const float* Qg = Q + ((size_t)h * S_LEN + (size_t)qb * BQ) * DKH;
    const float* Kg = K + (size_t)h * S_LEN * DKH;
    const float* Vg = V + (size_t)h * S_LEN * DKH;

    // Load + convert Q tile (128x64) once
#pragma unroll
    for (int p = 0; p < 8; p++) {
        int f   = tid + p * 256;
        int row = f >> 4;
        int col = (f & 15) * 4;
        float4 v4 = *(const float4*)(Qg + (size_t)row * DKH + col);
        Qs[row * LQ + col + 0] = f2tf32f(v4.x);
        Qs[row * LQ + col + 1] = f2tf32f(v4.y);
        Qs[row * LQ + col + 2] = f2tf32f(v4.z);
        Qs[row * LQ + col + 3] = f2tf32f(v4.w);
    }

    float m0 = -INFINITY, m1 = -INFINITY, l0 = 0.f, l1 = 0.f;
    float o[8][4];
#pragma unroll
    for (int nt = 0; nt < 8; nt++)
#pragma unroll
        for (int j = 0; j < 4; j++) o[nt][j] = 0.f;

    const int row0 = qb * BQ + w16 + g;
    const int row1 = row0 + 8;
    const unsigned long long* mb0p = mbits + (size_t)row0 * 64;
    const unsigned long long* mb1p = mbits + (size_t)row1 * 64;

    for (int kb = 0; kb < S_LEN / BKC; kb++) {
        // packed mask words for this 64-col block (pre-shifted by 2*tig)
        const unsigned long long b0 = mb0p[kb] >> (2 * tig);
        const unsigned long long b1 = mb1p[kb] >> (2 * tig);

        __syncthreads();                      // prev-iter smem reads complete
#pragma unroll
        for (int p = 0; p < 4; p++) {
            int f   = tid + p * 256;
            int row = f >> 4;
            int col = (f & 15) * 4;
            size_t goff = (size_t)(kb * BKC + row) * DKH + col;
            float4 kv4 = *(const float4*)(Kg + goff);
            float4 vv4 = *(const float4*)(Vg + goff);
            Ks[row * LK + col + 0] = f2tf32f(kv4.x);
            Ks[row * LK + col + 1] = f2tf32f(kv4.y);
            Ks[row * LK + col + 2] = f2tf32f(kv4.z);
            Ks[row * LK + col + 3] = f2tf32f(kv4.w);
            Vs[row * LV + col + 0] = f2tf32f(vv4.x);
            Vs[row * LV + col + 1] = f2tf32f(vv4.y);
            Vs[row * LV + col + 2] = f2tf32f(vv4.z);
            Vs[row * LV + col + 3] = f2tf32f(vv4.w);
        }
        __syncthreads();

        // ---- S = Q * K^T ----
        float s[8][4];
#pragma unroll
        for (int nt = 0; nt < 8; nt++)
#pragma unroll
            for (int j = 0; j < 4; j++) s[nt][j] = 0.f;

#pragma unroll
        for (int kk = 0; kk < 8; kk++) {
            unsigned a0 = __float_as_uint(Qs[(w16 + g)     * LQ + kk * 8 + tig]);
            unsigned a1 = __float_as_uint(Qs[(w16 + g + 8) * LQ + kk * 8 + tig]);
            unsigned a2 = __float_as_uint(Qs[(w16 + g)     * LQ + kk * 8 + tig + 4]);
            unsigned a3 = __float_as_uint(Qs[(w16 + g + 8) * LQ + kk * 8 + tig + 4]);
#pragma unroll
            for (int nt = 0; nt < 8; nt++) {
                unsigned bb0 = __float_as_uint(Ks[(nt * 8 + g) * LK + kk * 8 + tig]);
                unsigned bb1 = __float_as_uint(Ks[(nt * 8 + g) * LK + kk * 8 + tig + 4]);
                mma_tf32(s[nt], a0, a1, a2, a3, bb0, bb1);
            }
        }

        // ---- mask (bit test) + online softmax ----
        float mx0 = -INFINITY, mx1 = -INFINITY;
#pragma unroll
        for (int nt = 0; nt < 8; nt++) {
            s[nt][0] = s[nt][0] * 0.125f + (((b0 >> (nt * 8    )) & 1ull) ? -1e9f : 0.f);
            s[nt][1] = s[nt][1] * 0.125f + (((b0 >> (nt * 8 + 1)) & 1ull) ? -1e9f : 0.f);
            s[nt][2] = s[nt][2] * 0.125f + (((b1 >> (nt * 8    )) & 1ull) ? -1e9f : 0.f);
            s[nt][3] = s[nt][3] * 0.125f + (((b1 >> (nt * 8 + 1)) & 1ull) ? -1e9f : 0.f);
            mx0 = fmaxf(mx0, fmaxf(s[nt][0], s[nt][1]));
            mx1 = fmaxf(mx1, fmaxf(s[nt][2], s[nt][3]));
        }
        mx0 = fmaxf(mx0, __shfl_xor_sync(0xffffffffu, mx0, 1));
        mx0 = fmaxf(mx0, __shfl_xor_sync(0xffffffffu, mx0, 2));
        mx1 = fmaxf(mx1, __shfl_xor_sync(0xffffffffu, mx1, 1));
        mx1 = fmaxf(mx1, __shfl_xor_sync(0xffffffffu, mx1, 2));

        float mn0 = fmaxf(m0, mx0), mn1 = fmaxf(m1, mx1);
        float sc0 = __expf(m0 - mn0), sc1 = __expf(m1 - mn1);
        m0 = mn0; m1 = mn1;

        float rs0 = 0.f, rs1 = 0.f;
#pragma unroll
        for (int nt = 0; nt < 8; nt++) {
            float p0 = __expf(s[nt][0] - mn0);
            float p1 = __expf(s[nt][1] - mn0);
            float p2 = __expf(s[nt][2] - mn1);
            float p3 = __expf(s[nt][3] - mn1);
            rs0 += p0 + p1;
            rs1 += p2 + p3;
            *(float2*)&Ps[(w16 + g)     * LP + nt * 8 + 2 * tig] =
                make_float2(f2tf32f(p0), f2tf32f(p1));
            *(float2*)&Ps[(w16 + g + 8) * LP + nt * 8 + 2 * tig] =
                make_float2(f2tf32f(p2), f2tf32f(p3));
            o[nt][0] *= sc0; o[nt][1] *= sc0;
            o[nt][2] *= sc1; o[nt][3] *= sc1;
        }
        rs0 += __shfl_xor_sync(0xffffffffu, rs0, 1);
        rs0 += __shfl_xor_sync(0xffffffffu, rs0, 2);
        rs1 += __shfl_xor_sync(0xffffffffu, rs1, 1);
        rs1 += __shfl_xor_sync(0xffffffffu, rs1, 2);
        l0 = l0 * sc0 + rs0;
        l1 = l1 * sc1 + rs1;

        __syncwarp();   // P stores visible within warp (only this warp reads)

        // ---- O += P * V ----
#pragma unroll
        for (int kc = 0; kc < 8; kc++) {
            unsigned a0 = __float_as_uint(Ps[(w16 + g)     * LP + kc * 8 + tig]);
            unsigned a1 = __float_as_uint(Ps[(w16 + g + 8) * LP + kc * 8 + tig]);
            unsigned a2 = __float_as_uint(Ps[(w16 + g)     * LP + kc * 8 + tig + 4]);
            unsigned a3 = __float_as_uint(Ps[(w16 + g + 8) * LP + kc * 8 + tig + 4]);
#pragma unroll
            for (int nt = 0; nt < 8; nt++) {
                unsigned bb0 = __float_as_uint(Vs[(kc * 8 + tig)     * LV + nt * 8 + g]);
                unsigned bb1 = __float_as_uint(Vs[(kc * 8 + tig + 4) * LV + nt * 8 + g]);
                mma_tf32(o[nt], a0, a1, a2, a3, bb0, bb1);
            }
        }
    }

    // Normalize + write AttnOut[token][h*64 + d]
    float inv0 = 1.0f / l0, inv1 = 1.0f / l1;
    float* O0 = O + (size_t)row0 * DMODEL + h * DKH + 2 * tig;
    float* O1 = O + (size_t)row1 * DMODEL + h * DKH + 2 * tig;
#pragma unroll
    for (int nt = 0; nt < 8; nt++) {
        *(float2*)(O0 + nt * 8) = make_float2(o[nt][0] * inv0, o[nt][1] * inv0);
        *(float2*)(O1 + nt * 8) = make_float2(o[nt][2] * inv1, o[nt][3] * inv1);
    }
}

// ============================================================================
extern "C" void kernel_launch(void* const* d_in, const int* in_sizes, int n_in,
                              void* d_out, int out_size)
{
    const float* x       = (const float*)d_in[0];
    const int*   mask    = (const int*)  d_in[1];
    const float* wq_w    = (const float*)d_in[2];
    const float* wq_b    = (const float*)d_in[3];
    const float* wk_w    = (const float*)d_in[4];
    const float* wk_b    = (const float*)d_in[5];
    const float* wv_w    = (const float*)d_in[6];
    const float* wv_b    = (const float*)d_in[7];
    const float* dense_w = (const float*)d_in[8];
    const float* dense_b = (const float*)d_in[9];
    float* out = (float*)d_out;

    float *Qp, *Kp, *Vp, *AOp;
    unsigned long long* MBp;
    cudaGetSymbolAddress((void**)&Qp,  g_Q);
    cudaGetSymbolAddress((void**)&Kp,  g_K);
    cudaGetSymbolAddress((void**)&Vp,  g_V);
    cudaGetSymbolAddress((void**)&AOp, g_AO);
    cudaGetSymbolAddress((void**)&MBp, g_MB);

    cudaFuncSetAttribute(attn_tc_kernel,
                         cudaFuncAttributeMaxDynamicSharedMemorySize,
                         ATTN_SMEM_BYTES);

    // 0) Bit-pack the mask (S*S int32 -> S x S/64 uint64, 2 MB, L2-resident)
    pack_mask_kernel<<<(S_LEN * 64 * 32) / 256, 256>>>(mask, MBp);

    // 1) Fused QKV projections (tf32 tensor cores)
    qkv_gemm_kernel<<<dim3(12, S_LEN / 128), 256>>>(
        x, wq_w, wq_b, wk_w, wk_b, wv_w, wv_b, Qp, Kp, Vp);

    // 2) Masked flash attention on tensor cores (tf32), 2 CTAs/SM
    attn_tc_kernel<<<dim3(S_LEN / BQ, NHEAD), 256, ATTN_SMEM_BYTES>>>(
        Qp, Kp, Vp, MBp, AOp);

    // 3) Dense output projection (tf32 tensor cores)
    dense_gemm_kernel<<<dim3(DMODEL / 128, S_LEN / 128), 256>>>(
        AOp, dense_w, dense_b, out);
}